// round 14
// baseline (speedup 1.0000x reference)
#include <cuda_runtime.h>
#include <cuda_fp16.h>
#include <math.h>
#include <stdint.h>

#define ROWS 131072
#define HID 256
#define OBS_DIM 128
#define N_ACTIONS 32
#define N_AGENTS 16
#define NGROUP (ROWS / N_AGENTS)

// -------- scratch --------
__device__ __half g_x16 [ROWS * HID];
__device__ __half g_h16a[ROWS * HID];
__device__ __half g_h16b[ROWS * HID];
__device__ __half g_obs16[ROWS * OBS_DIM];
__device__ __half g_h016[ROWS * HID];
__device__ __half g_wf  [1024 * 512];
__device__ __half g_wf2 [1024 * 256];
__device__ __half g_ws16[768 * 256];
__device__ float  g_gb  [1024];
__device__ __half g_S16 [NGROUP * HID];
__device__ float  g_Sg  [NGROUP * 768];
__device__ __half g_encw[HID * OBS_DIM];
__device__ __half g_decw[N_ACTIONS * HID];

// ===== geometry: CTA 128x128, 8 warps @ 32x64, K-chunk 64, double buffer =====
#define FPITCH 72
#define FCHUNK (128 * FPITCH)
#define FSMEM_BYTES (4 * FCHUNK * 2)     /* 73728 B -> 2 CTAs/SM */

__device__ __forceinline__ void mma_f16(float* d, const uint32_t* a, const uint32_t* b) {
    asm volatile(
        "mma.sync.aligned.m16n8k16.row.col.f32.f16.f16.f32 "
        "{%0,%1,%2,%3}, {%4,%5,%6,%7}, {%8,%9}, {%0,%1,%2,%3};"
        : "+f"(d[0]), "+f"(d[1]), "+f"(d[2]), "+f"(d[3])
        : "r"(a[0]), "r"(a[1]), "r"(a[2]), "r"(a[3]), "r"(b[0]), "r"(b[1]));
}
__device__ __forceinline__ void ldsm4(uint32_t* r, uint32_t addr) {
    asm volatile("ldmatrix.sync.aligned.m8n8.x4.shared.b16 {%0,%1,%2,%3}, [%4];"
        : "=r"(r[0]), "=r"(r[1]), "=r"(r[2]), "=r"(r[3]) : "r"(addr));
}
__device__ __forceinline__ float sigf(float u) {
    float e = __expf(-u);
    return __fdividef(1.0f, 1.0f + e);
}
__device__ __forceinline__ float tanhfast(float t) {
    float e = __expf(-2.0f * fabsf(t));
    return copysignf(__fdividef(1.0f - e, 1.0f + e), t);
}
__device__ __forceinline__ void cpa16(uint32_t dst, const void* src) {
    asm volatile("cp.async.cg.shared.global [%0], [%1], 16;" :: "r"(dst), "l"(src));
}
__device__ __forceinline__ void pref_l2(const void* p) {
    asm volatile("prefetch.global.L2 [%0];" :: "l"(p));
}

// one K=64 chunk via ldmatrix; SKIPG = gate col (nt&3) to skip, or -1
template<int SKIPG>
__device__ __forceinline__ void compute_chunk(uint32_t sa, uint32_t sb,
                                              float (&d)[2][8][4],
                                              uint32_t aoff, uint32_t boff)
{
#pragma unroll
    for (int ks = 0; ks < 4; ks++) {
        uint32_t a[2][4];
#pragma unroll
        for (int mt = 0; mt < 2; mt++)
            ldsm4(a[mt], sa + aoff + (mt * 16 * FPITCH + ks * 16) * 2);
        uint32_t b[8][2];
#pragma unroll
        for (int np = 0; np < 4; np++) {
            uint32_t r[4];
            ldsm4(r, sb + boff + (np * 16 * FPITCH + ks * 16) * 2);
            b[2 * np][0] = r[0]; b[2 * np][1] = r[1];
            b[2 * np + 1][0] = r[2]; b[2 * np + 1][1] = r[3];
        }
#pragma unroll
        for (int mt = 0; mt < 2; mt++)
#pragma unroll
            for (int nt = 0; nt < 8; nt++) {
                if (SKIPG >= 0 && (nt & 3) == SKIPG) continue;
                mma_f16(d[mt][nt], a[mt], b[nt]);
            }
    }
}

// GRU epilogue; fp16 hprev; Sg optional; optional fp32 h out; optional fused group-sum.
__device__ __forceinline__ void gru_epilogue(
    float (&d)[2][8][4], const __half* hp16,
    const float* Sg, float* h32out, __half* h16out,
    __half* Ssum, float* smf,
    int row0, int col0, int wm, int wn, int gq, int tig, int tid)
{
    const float* gb = g_gb;
    const int J0 = col0 >> 2;
#pragma unroll
    for (int a2 = 0; a2 < 2; a2++) {
        const int J = J0 + wn * 16 + a2 * 8 + 2 * tig;
        const float bR0 = gb[J],       bR1 = gb[J + 1];
        const float bZ0 = gb[256 + J], bZ1 = gb[256 + J + 1];
        const float bI0 = gb[512 + J], bI1 = gb[512 + J + 1];
        const float bH0 = gb[768 + J], bH1 = gb[768 + J + 1];
#pragma unroll
        for (int mt = 0; mt < 2; mt++) {
            const int rowa = row0 + wm * 32 + mt * 16 + gq;
#pragma unroll
            for (int half = 0; half < 2; half++) {
                const int row = rowa + half * 8;
                const int e0 = half * 2, e1 = half * 2 + 1;
                float sRx = 0.f, sRy = 0.f, sZx = 0.f, sZy = 0.f, sIx = 0.f, sIy = 0.f;
                if (Sg) {
                    const float* sgr = Sg + (size_t)(row >> 4) * 768 + J;
                    float2 t;
                    t = *(const float2*)(sgr);        sRx = t.x; sRy = t.y;
                    t = *(const float2*)(sgr + 256);  sZx = t.x; sZy = t.y;
                    t = *(const float2*)(sgr + 512);  sIx = t.x; sIy = t.y;
                }
                float r0 = sigf(d[mt][4 * a2 + 0][e0] + sRx + bR0);
                float r1 = sigf(d[mt][4 * a2 + 0][e1] + sRy + bR1);
                float z0 = sigf(d[mt][4 * a2 + 1][e0] + sZx + bZ0);
                float z1 = sigf(d[mt][4 * a2 + 1][e1] + sZy + bZ1);
                float n0 = tanhfast(d[mt][4 * a2 + 2][e0] + sIx + bI0 + r0 * (d[mt][4 * a2 + 3][e0] + bH0));
                float n1 = tanhfast(d[mt][4 * a2 + 2][e1] + sIy + bI1 + r1 * (d[mt][4 * a2 + 3][e1] + bH1));
                float2 hp = __half22float2(*(const __half2*)(hp16 + (size_t)row * HID + J));
                float h0 = (1.0f - z0) * n0 + z0 * hp.x;
                float h1 = (1.0f - z1) * n1 + z1 * hp.y;
                if (h32out) *(float2*)(h32out + (size_t)row * HID + J) = make_float2(h0, h1);
                *(__half2*)(h16out + (size_t)row * HID + J) = __floats2half2_rn(h0, h1);
                if (Ssum) {
                    const int lr = row - row0, lc = J - J0;
                    smf[lr * 33 + lc]     = h0;
                    smf[lr * 33 + lc + 1] = h1;
                }
            }
        }
    }
    if (Ssum) {
        __syncthreads();
        const int g = tid >> 5, c = tid & 31;
        float s = 0.f;
#pragma unroll
        for (int i = 0; i < 16; i++)
            s += smf[(g * 16 + i) * 33 + c];
        Ssum[(size_t)((row0 >> 4) + g) * HID + J0 + c] = __float2half_rn(s);
    }
}

#define FRAG_OFFSETS                                                            \
    const int rA = (lid & 7) + ((lid >> 3) & 1) * 8, kA = ((lid >> 4) & 1) * 8; \
    const int rB = (lid & 7) + ((lid >> 4) & 1) * 8, kB = ((lid >> 3) & 1) * 8; \
    const uint32_t aoff = ((wm * 32 + rA) * FPITCH + kA) * 2;                   \
    const uint32_t boff = ((wn * 64 + rB) * FPITCH + kB) * 2;

#define ACC_INIT                                                                \
    float d[2][8][4];                                                           \
    _Pragma("unroll")                                                           \
    for (int mt = 0; mt < 2; mt++)                                              \
        _Pragma("unroll")                                                       \
        for (int nt = 0; nt < 8; nt++)                                          \
            _Pragma("unroll")                                                   \
            for (int e = 0; e < 4; e++) d[mt][nt][e] = 0.0f;

// prefetch the epilogue inputs for this CTA's tile into L2 (each thread: 2 lines)
#define EPI_PREFETCH(hp, SgP) do {                                              \
        int pr_ = row0 + (tid >> 1);                                            \
        pref_l2((hp) + (size_t)pr_ * HID + (tid & 1) * 128);                    \
        if (SgP && tid < 128) {                                                 \
            int gg_ = (row0 >> 4) + (tid >> 4);                                 \
            pref_l2((const float*)(SgP) + (size_t)gg_ * 768 + (tid & 15) * 48); \
        }                                                                       \
    } while (0)

// ---- cell 1: A = [x | h] (K=512), gate-skip per phase; fused group-sum ----
__global__ __launch_bounds__(256, 2)
void fused_gru(const __half* __restrict__ Ax, const __half* __restrict__ Ah,
               const __half* __restrict__ hp16, __half* __restrict__ h16out,
               __half* __restrict__ Ssum)
{
    extern __shared__ __half sm[];
    const uint32_t s0 = (uint32_t)__cvta_generic_to_shared(sm);
    const uint32_t sB0 = s0 + 2 * FCHUNK * 2;
    const int tid = threadIdx.x, wid = tid >> 5, lid = tid & 31;
    const int wm = wid & 3, wn = wid >> 2;
    const int gq = lid >> 2, tig = lid & 3;
    const int row0 = blockIdx.y * 128, col0 = blockIdx.x * 128;
    FRAG_OFFSETS
    ACC_INIT

#define LD1(kc) do {                                                            \
        uint32_t ba_ = s0 + ((kc) & 1) * FCHUNK * 2;                            \
        uint32_t bb_ = sB0 + ((kc) & 1) * FCHUNK * 2;                           \
        const __half* as_ = ((kc) < 4) ? Ax + (size_t)row0 * HID + (kc) * 64    \
                                       : Ah + (size_t)row0 * HID + ((kc)-4)*64; \
        _Pragma("unroll")                                                       \
        for (int i_ = 0; i_ < 4; i_++) {                                        \
            int idx_ = tid + i_ * 256;                                          \
            int r_ = idx_ >> 3, q_ = idx_ & 7;                                  \
            cpa16(ba_ + (r_ * FPITCH + q_ * 8) * 2, as_ + (size_t)r_ * HID + q_ * 8); \
            cpa16(bb_ + (r_ * FPITCH + q_ * 8) * 2,                             \
                  g_wf + (size_t)(col0 + r_) * 512 + (kc) * 64 + q_ * 8);       \
        }                                                                       \
        asm volatile("cp.async.commit_group;");                                 \
    } while (0)

    LD1(0);
    EPI_PREFETCH(hp16, (const float*)0);
#pragma unroll
    for (int kc = 0; kc < 8; kc++) {
        if (kc + 1 < 8) { LD1(kc + 1); asm volatile("cp.async.wait_group 1;"); }
        else            { asm volatile("cp.async.wait_group 0;"); }
        __syncthreads();
        uint32_t ba = s0 + (kc & 1) * FCHUNK * 2;
        uint32_t bb = sB0 + (kc & 1) * FCHUNK * 2;
        if (kc < 4) compute_chunk<3>(ba, bb, d, aoff, boff);
        else        compute_chunk<2>(ba, bb, d, aoff, boff);
        __syncthreads();
    }
#undef LD1
    gru_epilogue(d, hp16, nullptr, nullptr, h16out, Ssum, (float*)sm,
                 row0, col0, wm, wn, gq, tig, tid);
}

// ---- cells 2/3: gates = h @ Wf2 + Sg[row/16] + bias (K=256); optional fused sum ----
__global__ __launch_bounds__(256, 2)
void fused_gru2(const __half* __restrict__ Ah, const __half* __restrict__ hp16,
                const float* __restrict__ Sg,
                float* __restrict__ h32out, __half* __restrict__ h16out,
                __half* __restrict__ Ssum)
{
    extern __shared__ __half sm[];
    const uint32_t s0 = (uint32_t)__cvta_generic_to_shared(sm);
    const uint32_t sB0 = s0 + 2 * FCHUNK * 2;
    const int tid = threadIdx.x, wid = tid >> 5, lid = tid & 31;
    const int wm = wid & 3, wn = wid >> 2;
    const int gq = lid >> 2, tig = lid & 3;
    const int row0 = blockIdx.y * 128, col0 = blockIdx.x * 128;
    FRAG_OFFSETS
    ACC_INIT

#define LD2(kc) do {                                                            \
        uint32_t ba_ = s0 + ((kc) & 1) * FCHUNK * 2;                            \
        uint32_t bb_ = sB0 + ((kc) & 1) * FCHUNK * 2;                           \
        _Pragma("unroll")                                                       \
        for (int i_ = 0; i_ < 4; i_++) {                                        \
            int idx_ = tid + i_ * 256;                                          \
            int r_ = idx_ >> 3, q_ = idx_ & 7;                                  \
            cpa16(ba_ + (r_ * FPITCH + q_ * 8) * 2,                             \
                  Ah + (size_t)(row0 + r_) * HID + (kc) * 64 + q_ * 8);         \
            cpa16(bb_ + (r_ * FPITCH + q_ * 8) * 2,                             \
                  g_wf2 + (size_t)(col0 + r_) * 256 + (kc) * 64 + q_ * 8);      \
        }                                                                       \
        asm volatile("cp.async.commit_group;");                                 \
    } while (0)

    LD2(0);
    EPI_PREFETCH(hp16, Sg);
#pragma unroll
    for (int kc = 0; kc < 4; kc++) {
        if (kc + 1 < 4) { LD2(kc + 1); asm volatile("cp.async.wait_group 1;"); }
        else            { asm volatile("cp.async.wait_group 0;"); }
        __syncthreads();
        uint32_t ba = s0 + (kc & 1) * FCHUNK * 2;
        uint32_t bb = sB0 + (kc & 1) * FCHUNK * 2;
        compute_chunk<-1>(ba, bb, d, aoff, boff);
        __syncthreads();
    }
#undef LD2
    gru_epilogue(d, hp16, Sg, h32out, h16out, Ssum, (float*)sm,
                 row0, col0, wm, wn, gq, tig, tid);
}

// ---- encoder: 2 row-tiles per CTA, B (encW slice) resident; K=128 ----
__global__ __launch_bounds__(256, 2)
void enc2(const __half* __restrict__ A, const float* __restrict__ bias,
          __half* __restrict__ C16)
{
    extern __shared__ __half sm[];
    const uint32_t s0 = (uint32_t)__cvta_generic_to_shared(sm);
    const uint32_t sB0 = s0 + 2 * FCHUNK * 2;
    const int tid = threadIdx.x, wid = tid >> 5, lid = tid & 31;
    const int wm = wid & 3, wn = wid >> 2;
    const int gq = lid >> 2, tig = lid & 3;
    const int col0 = blockIdx.x * 128;
    FRAG_OFFSETS

    {
#pragma unroll
        for (int kc = 0; kc < 2; kc++) {
            uint32_t bb_ = sB0 + kc * FCHUNK * 2;
#pragma unroll
            for (int i_ = 0; i_ < 4; i_++) {
                int idx_ = tid + i_ * 256;
                int r_ = idx_ >> 3, q_ = idx_ & 7;
                cpa16(bb_ + (r_ * FPITCH + q_ * 8) * 2,
                      g_encw + (size_t)(col0 + r_) * OBS_DIM + kc * 64 + q_ * 8);
            }
        }
        asm volatile("cp.async.commit_group;");
    }

#define LDA_(it) do {                                                           \
        uint32_t ba_ = s0 + ((it) & 1) * FCHUNK * 2;                            \
        int r0_ = blockIdx.y * 256 + ((it) >> 1) * 128;                         \
        _Pragma("unroll")                                                       \
        for (int i_ = 0; i_ < 4; i_++) {                                        \
            int idx_ = tid + i_ * 256;                                          \
            int r_ = idx_ >> 3, q_ = idx_ & 7;                                  \
            cpa16(ba_ + (r_ * FPITCH + q_ * 8) * 2,                             \
                  A + (size_t)(r0_ + r_) * OBS_DIM + ((it) & 1) * 64 + q_ * 8); \
        }                                                                       \
        asm volatile("cp.async.commit_group;");                                 \
    } while (0)

    LDA_(0);
    ACC_INIT
#pragma unroll
    for (int it = 0; it < 4; it++) {
        if (it + 1 < 4) { LDA_(it + 1); asm volatile("cp.async.wait_group 1;"); }
        else            { asm volatile("cp.async.wait_group 0;"); }
        __syncthreads();
        uint32_t ba = s0 + (it & 1) * FCHUNK * 2;
        uint32_t bb = sB0 + (it & 1) * FCHUNK * 2;
        compute_chunk<-1>(ba, bb, d, aoff, boff);
        __syncthreads();

        if (it & 1) {
            int row0 = blockIdx.y * 256 + (it >> 1) * 128;
#pragma unroll
            for (int nt = 0; nt < 8; nt++) {
                int col = col0 + wn * 64 + nt * 8 + 2 * tig;
                float b0 = bias[col], b1 = bias[col + 1];
#pragma unroll
                for (int mt = 0; mt < 2; mt++) {
                    int rowa = row0 + wm * 32 + mt * 16 + gq;
#pragma unroll
                    for (int half = 0; half < 2; half++) {
                        int row = rowa + half * 8;
                        float v0 = sigf(d[mt][nt][half * 2]     + b0);
                        float v1 = sigf(d[mt][nt][half * 2 + 1] + b1);
                        *(__half2*)(C16 + (size_t)row * HID + col) = __floats2half2_rn(v0, v1);
                    }
                }
            }
            if (it == 1) {
#pragma unroll
                for (int mt = 0; mt < 2; mt++)
#pragma unroll
                    for (int nt = 0; nt < 8; nt++)
#pragma unroll
                        for (int e = 0; e < 4; e++) d[mt][nt][e] = 0.0f;
            }
        }
    }
#undef LDA_
}

// ---- Sg GEMM: CTA 64x128, 4 warps @ 32x64, 128 threads, K=256, N=768 exact ----
#define SGA_BYTES (64 * FPITCH * 2)
#define SGB_BYTES (128 * FPITCH * 2)
#define SG_SMEM (2 * (SGA_BYTES + SGB_BYTES))

__global__ __launch_bounds__(128, 4)
void hgemm64(const __half* __restrict__ A, const __half* __restrict__ W,
             float* __restrict__ C32)
{
    extern __shared__ __half sm[];
    const uint32_t s0 = (uint32_t)__cvta_generic_to_shared(sm);
    const uint32_t sB0 = s0 + 2 * SGA_BYTES;
    const int tid = threadIdx.x, wid = tid >> 5, lid = tid & 31;
    const int wm = wid & 1, wn = wid >> 1;
    const int gq = lid >> 2, tig = lid & 3;
    const int row0 = blockIdx.y * 64, col0 = blockIdx.x * 128;
    FRAG_OFFSETS
    ACC_INIT

#define LDS_(kc) do {                                                           \
        uint32_t ba_ = s0 + ((kc) & 1) * SGA_BYTES;                             \
        uint32_t bb_ = sB0 + ((kc) & 1) * SGB_BYTES;                            \
        _Pragma("unroll")                                                       \
        for (int i_ = 0; i_ < 4; i_++) {                                        \
            int idx_ = tid + i_ * 128;                                          \
            int r_ = idx_ >> 3, q_ = idx_ & 7;                                  \
            cpa16(ba_ + (r_ * FPITCH + q_ * 8) * 2,                             \
                  A + (size_t)(row0 + r_) * HID + (kc) * 64 + q_ * 8);          \
        }                                                                       \
        _Pragma("unroll")                                                       \
        for (int i_ = 0; i_ < 8; i_++) {                                        \
            int idx_ = tid + i_ * 128;                                          \
            int r_ = idx_ >> 3, q_ = idx_ & 7;                                  \
            cpa16(bb_ + (r_ * FPITCH + q_ * 8) * 2,                             \
                  W + (size_t)(col0 + r_) * HID + (kc) * 64 + q_ * 8);          \
        }                                                                       \
        asm volatile("cp.async.commit_group;");                                 \
    } while (0)

    LDS_(0);
#pragma unroll
    for (int kc = 0; kc < 4; kc++) {
        if (kc + 1 < 4) { LDS_(kc + 1); asm volatile("cp.async.wait_group 1;"); }
        else            { asm volatile("cp.async.wait_group 0;"); }
        __syncthreads();
        uint32_t ba = s0 + (kc & 1) * SGA_BYTES;
        uint32_t bb = sB0 + (kc & 1) * SGB_BYTES;
        compute_chunk<-1>(ba, bb, d, aoff, boff);
        __syncthreads();
    }
#undef LDS_

#pragma unroll
    for (int nt = 0; nt < 8; nt++) {
        int col = col0 + wn * 64 + nt * 8 + 2 * tig;
#pragma unroll
        for (int mt = 0; mt < 2; mt++) {
            int rowa = row0 + wm * 32 + mt * 16 + gq;
#pragma unroll
            for (int half = 0; half < 2; half++) {
                int row = rowa + half * 8;
                *(float2*)(C32 + (size_t)row * 768 + col) =
                    make_float2(d[mt][nt][half * 2], d[mt][nt][half * 2 + 1]);
            }
        }
    }
}

// ---- decoder GEMM: CTA 256x32, 8 warps (32 rows x 32 cols each), K=256 ----
#define DA_BYTES (256 * FPITCH * 2)
#define DB_BYTES (32 * FPITCH * 2)
#define DEC_SMEM (2 * (DA_BYTES + DB_BYTES))

__global__ __launch_bounds__(256, 2)
void dec_gemm(const __half* __restrict__ A, const float* __restrict__ bias,
              float* __restrict__ C)
{
    extern __shared__ __half sm[];
    const uint32_t s0 = (uint32_t)__cvta_generic_to_shared(sm);
    const uint32_t sB0 = s0 + 2 * DA_BYTES;
    const int tid = threadIdx.x, wid = tid >> 5, lid = tid & 31;
    const int gq = lid >> 2, tig = lid & 3;
    const int row0 = blockIdx.y * 256;
    const int rA = (lid & 7) + ((lid >> 3) & 1) * 8, kA = ((lid >> 4) & 1) * 8;
    const int rB = (lid & 7) + ((lid >> 4) & 1) * 8, kB = ((lid >> 3) & 1) * 8;
    const uint32_t aoff = ((wid * 32 + rA) * FPITCH + kA) * 2;
    const uint32_t boff = (rB * FPITCH + kB) * 2;

    float d[2][4][4];
#pragma unroll
    for (int mt = 0; mt < 2; mt++)
#pragma unroll
        for (int nt = 0; nt < 4; nt++)
#pragma unroll
            for (int e = 0; e < 4; e++) d[mt][nt][e] = 0.0f;

#define LDD_(kc) do {                                                           \
        uint32_t ba_ = s0 + ((kc) & 1) * DA_BYTES;                              \
        uint32_t bb_ = sB0 + ((kc) & 1) * DB_BYTES;                             \
        _Pragma("unroll")                                                       \
        for (int i_ = 0; i_ < 8; i_++) {                                        \
            int idx_ = tid + i_ * 256;                                          \
            int r_ = idx_ >> 3, q_ = idx_ & 7;                                  \
            cpa16(ba_ + (r_ * FPITCH + q_ * 8) * 2,                             \
                  A + (size_t)(row0 + r_) * HID + (kc) * 64 + q_ * 8);          \
        }                                                                       \
        { int r_ = tid >> 3, q_ = tid & 7;                                      \
          cpa16(bb_ + (r_ * FPITCH + q_ * 8) * 2,                               \
                g_decw + (size_t)r_ * HID + (kc) * 64 + q_ * 8); }              \
        asm volatile("cp.async.commit_group;");                                 \
    } while (0)

    LDD_(0);
#pragma unroll
    for (int kc = 0; kc < 4; kc++) {
        if (kc + 1 < 4) { LDD_(kc + 1); asm volatile("cp.async.wait_group 1;"); }
        else            { asm volatile("cp.async.wait_group 0;"); }
        __syncthreads();
        uint32_t ba = s0 + (kc & 1) * DA_BYTES;
        uint32_t bb = sB0 + (kc & 1) * DB_BYTES;
#pragma unroll
        for (int ks = 0; ks < 4; ks++) {
            uint32_t a[2][4];
#pragma unroll
            for (int mt = 0; mt < 2; mt++)
                ldsm4(a[mt], ba + aoff + (mt * 16 * FPITCH + ks * 16) * 2);
            uint32_t b[4][2];
#pragma unroll
            for (int np = 0; np < 2; np++) {
                uint32_t r[4];
                ldsm4(r, bb + boff + (np * 16 * FPITCH + ks * 16) * 2);
                b[2 * np][0] = r[0]; b[2 * np][1] = r[1];
                b[2 * np + 1][0] = r[2]; b[2 * np + 1][1] = r[3];
            }
#pragma unroll
            for (int mt = 0; mt < 2; mt++)
#pragma unroll
                for (int nt = 0; nt < 4; nt++)
                    mma_f16(d[mt][nt], a[mt], b[nt]);
        }
        __syncthreads();
    }
#undef LDD_

#pragma unroll
    for (int nt = 0; nt < 4; nt++) {
        int col = nt * 8 + 2 * tig;
        float b0 = bias[col], b1 = bias[col + 1];
#pragma unroll
        for (int mt = 0; mt < 2; mt++) {
            int rowa = row0 + wid * 32 + mt * 16 + gq;
#pragma unroll
            for (int half = 0; half < 2; half++) {
                int row = rowa + half * 8;
                *(float2*)(C + (size_t)row * N_ACTIONS + col) =
                    make_float2(d[mt][nt][half * 2] + b0, d[mt][nt][half * 2 + 1] + b1);
            }
        }
    }
}

// ================= split prep kernels =================
#define N_OBS4 (ROWS * OBS_DIM / 4)
#define N_H04  (ROWS * HID / 4)
#define PREP_MAIN_TOTAL (N_OBS4 + 32768)
#define PREP_REST_TOTAL (N_H04 + 524288 + 262144 + 196608 + 8192 + 1024)

__global__ void prep_main(const float* __restrict__ obs, const float* __restrict__ enc_w)
{
    int idx = blockIdx.x * blockDim.x + threadIdx.x;
    if (idx < N_OBS4) {
        float4 v = ((const float4*)obs)[idx];
        ((__half2*)g_obs16)[2 * idx]     = __floats2half2_rn(v.x, v.y);
        ((__half2*)g_obs16)[2 * idx + 1] = __floats2half2_rn(v.z, v.w);
        return;
    }
    idx -= N_OBS4;
    if (idx < 32768) g_encw[idx] = __float2half_rn(enc_w[idx]);
}

__global__ void prep_rest(const float* __restrict__ h0,
                          const float* __restrict__ w_ih, const float* __restrict__ w_hh,
                          const float* __restrict__ b_ih, const float* __restrict__ b_hh,
                          const float* __restrict__ dec_w)
{
    int idx = blockIdx.x * blockDim.x + threadIdx.x;
    const float inv = 1.0f / (float)N_AGENTS;
    if (idx < N_H04) {
        float4 v = ((const float4*)h0)[idx];
        ((__half2*)g_h016)[2 * idx]     = __floats2half2_rn(v.x, v.y);
        ((__half2*)g_h016)[2 * idx + 1] = __floats2half2_rn(v.z, v.w);
        return;
    }
    idx -= N_H04;
    if (idx < 524288) {
        int c = idx >> 9, k = idx & 511;
        int g = (c >> 3) & 3;
        int j = ((c >> 5) << 3) + (c & 7);
        float v;
        if (g == 0)      v = (k < 256) ? w_ih[j * 256 + k]         : w_hh[j * 256 + k - 256];
        else if (g == 1) v = (k < 256) ? w_ih[(256 + j) * 256 + k] : w_hh[(256 + j) * 256 + k - 256];
        else if (g == 2) v = (k < 256) ? w_ih[(512 + j) * 256 + k] : 0.0f;
        else             v = (k < 256) ? 0.0f                      : w_hh[(512 + j) * 256 + k - 256];
        g_wf[c * 512 + k] = __float2half_rn(v);
        return;
    }
    idx -= 524288;
    if (idx < 262144) {
        int c = idx >> 8, k = idx & 255;
        int g = (c >> 3) & 3;
        int j = ((c >> 5) << 3) + (c & 7);
        float v;
        if (g == 0)      v = w_hh[j * 256 + k]         - w_ih[j * 256 + k] * inv;
        else if (g == 1) v = w_hh[(256 + j) * 256 + k] - w_ih[(256 + j) * 256 + k] * inv;
        else if (g == 2) v = -w_ih[(512 + j) * 256 + k] * inv;
        else             v = w_hh[(512 + j) * 256 + k];
        g_wf2[c * 256 + k] = __float2half_rn(v);
        return;
    }
    idx -= 262144;
    if (idx < 196608) { g_ws16[idx] = __float2half_rn(w_ih[idx] * inv); return; }
    idx -= 196608;
    if (idx < 8192)   { g_decw[idx] = __float2half_rn(dec_w[idx]); return; }
    idx -= 8192;
    if (idx < 1024) {
        int g = idx >> 8, j = idx & 255;
        float v;
        if (g == 0)      v = b_ih[j] + b_hh[j];
        else if (g == 1) v = b_ih[256 + j] + b_hh[256 + j];
        else if (g == 2) v = b_ih[512 + j];
        else             v = b_hh[512 + j];
        g_gb[idx] = v;
    }
}

extern "C" void kernel_launch(void* const* d_in, const int* in_sizes, int n_in,
                              void* d_out, int out_size)
{
    const float* obs   = (const float*)d_in[0];
    const float* h0    = (const float*)d_in[1];
    const float* enc_w = (const float*)d_in[2];
    const float* enc_b = (const float*)d_in[3];
    const float* w_ih  = (const float*)d_in[4];
    const float* w_hh  = (const float*)d_in[5];
    const float* b_ih  = (const float*)d_in[6];
    const float* b_hh  = (const float*)d_in[7];
    const float* dec_w = (const float*)d_in[8];
    const float* dec_b = (const float*)d_in[9];
    float* out = (float*)d_out;

    __half *x16, *h16a, *h16b, *obs16, *h016, *ws16, *S16;
    float *Sg;
    cudaGetSymbolAddress((void**)&x16,   g_x16);
    cudaGetSymbolAddress((void**)&h16a,  g_h16a);
    cudaGetSymbolAddress((void**)&h16b,  g_h16b);
    cudaGetSymbolAddress((void**)&obs16, g_obs16);
    cudaGetSymbolAddress((void**)&h016,  g_h016);
    cudaGetSymbolAddress((void**)&ws16,  g_ws16);
    cudaGetSymbolAddress((void**)&S16,   g_S16);
    cudaGetSymbolAddress((void**)&Sg,    g_Sg);

    cudaFuncSetAttribute(fused_gru,  cudaFuncAttributeMaxDynamicSharedMemorySize, FSMEM_BYTES);
    cudaFuncSetAttribute(fused_gru2, cudaFuncAttributeMaxDynamicSharedMemorySize, FSMEM_BYTES);
    cudaFuncSetAttribute(enc2,       cudaFuncAttributeMaxDynamicSharedMemorySize, FSMEM_BYTES);
    cudaFuncSetAttribute(hgemm64,    cudaFuncAttributeMaxDynamicSharedMemorySize, SG_SMEM);
    cudaFuncSetAttribute(dec_gemm,   cudaFuncAttributeMaxDynamicSharedMemorySize, DEC_SMEM);

    dim3 t(256);

    cudaStream_t s2;
    cudaEvent_t evFork, evJoin;
    cudaStreamCreateWithFlags(&s2, cudaStreamNonBlocking);
    cudaEventCreateWithFlags(&evFork, cudaEventDisableTiming);
    cudaEventCreateWithFlags(&evJoin, cudaEventDisableTiming);

    cudaEventRecord(evFork, 0);
    cudaStreamWaitEvent(s2, evFork, 0);
    prep_rest<<<(PREP_REST_TOTAL + 255) / 256, 256, 0, s2>>>(h0, w_ih, w_hh, b_ih, b_hh, dec_w);
    cudaEventRecord(evJoin, s2);

    prep_main<<<(PREP_MAIN_TOTAL + 255) / 256, 256>>>(obs, enc_w);
    enc2<<<dim3(2, ROWS / 256), t, FSMEM_BYTES>>>(obs16, enc_b, x16);

    cudaStreamWaitEvent(0, evJoin, 0);

    // cell 1 (fp16 hprev = h016), fused group-sum -> S16
    fused_gru<<<dim3(8, ROWS / 128), t, FSMEM_BYTES>>>(x16, h016, h016, h16a, S16);

    // comm 1 GEMM + cell 2 (fused sum -> S16 for comm 2)
    hgemm64<<<dim3(6, NGROUP / 64), 128, SG_SMEM>>>(S16, ws16, Sg);
    fused_gru2<<<dim3(8, ROWS / 128), t, FSMEM_BYTES>>>(h16a, h16a, Sg, nullptr, h16b, S16);

    // comm 2 GEMM + cell 3 (fp32 h straight into d_out tail, no sum)
    hgemm64<<<dim3(6, NGROUP / 64), 128, SG_SMEM>>>(S16, ws16, Sg);
    fused_gru2<<<dim3(8, ROWS / 128), t, FSMEM_BYTES>>>(h16b, h16b, Sg,
                                                        out + (size_t)ROWS * N_ACTIONS, h16a, nullptr);

    // decoder (dedicated N=32 kernel)
    dec_gemm<<<dim3(1, ROWS / 256), t, DEC_SMEM>>>(h16a, dec_b, out);

    cudaEventDestroy(evFork);
    cudaEventDestroy(evJoin);
    cudaStreamDestroy(s2);
}

// round 15
// speedup vs baseline: 1.0606x; 1.0606x over previous
#include <cuda_runtime.h>
#include <cuda_fp16.h>
#include <math.h>
#include <stdint.h>

#define ROWS 131072
#define HID 256
#define OBS_DIM 128
#define N_ACTIONS 32
#define N_AGENTS 16
#define NGROUP (ROWS / N_AGENTS)

// -------- scratch --------
__device__ __half g_x16 [ROWS * HID];
__device__ __half g_h16a[ROWS * HID];
__device__ __half g_h16b[ROWS * HID];
__device__ __half g_obs16[ROWS * OBS_DIM];
__device__ __half g_h016[ROWS * HID];
__device__ __half g_wf  [1024 * 512];
__device__ __half g_wf2 [1024 * 256];
__device__ __half g_ws16[768 * 256];
__device__ float  g_gb  [1024];
__device__ __half g_S16 [NGROUP * HID];
__device__ float  g_Sg  [NGROUP * 768];
__device__ __half g_encw[HID * OBS_DIM];
__device__ __half g_decw[N_ACTIONS * HID];

// ===== geometry: CTA 128x128, 8 warps @ 32x64, K-chunk 64, double buffer =====
#define FPITCH 72
#define FCHUNK (128 * FPITCH)
#define FSMEM_BYTES (4 * FCHUNK * 2)     /* 73728 B -> 2 CTAs/SM */

__device__ __forceinline__ void mma_f16(float* d, const uint32_t* a, const uint32_t* b) {
    asm volatile(
        "mma.sync.aligned.m16n8k16.row.col.f32.f16.f16.f32 "
        "{%0,%1,%2,%3}, {%4,%5,%6,%7}, {%8,%9}, {%0,%1,%2,%3};"
        : "+f"(d[0]), "+f"(d[1]), "+f"(d[2]), "+f"(d[3])
        : "r"(a[0]), "r"(a[1]), "r"(a[2]), "r"(a[3]), "r"(b[0]), "r"(b[1]));
}
__device__ __forceinline__ void ldsm4(uint32_t* r, uint32_t addr) {
    asm volatile("ldmatrix.sync.aligned.m8n8.x4.shared.b16 {%0,%1,%2,%3}, [%4];"
        : "=r"(r[0]), "=r"(r[1]), "=r"(r[2]), "=r"(r[3]) : "r"(addr));
}
__device__ __forceinline__ float sigf(float u) {
    float e = __expf(-u);
    return __fdividef(1.0f, 1.0f + e);
}
__device__ __forceinline__ float tanhfast(float t) {
    float e = __expf(-2.0f * fabsf(t));
    return copysignf(__fdividef(1.0f - e, 1.0f + e), t);
}
__device__ __forceinline__ void cpa16(uint32_t dst, const void* src) {
    asm volatile("cp.async.cg.shared.global [%0], [%1], 16;" :: "r"(dst), "l"(src));
}

// one K=64 chunk via ldmatrix; SKIPG = gate col (nt&3) to skip, or -1
template<int SKIPG>
__device__ __forceinline__ void compute_chunk(uint32_t sa, uint32_t sb,
                                              float (&d)[2][8][4],
                                              uint32_t aoff, uint32_t boff)
{
#pragma unroll
    for (int ks = 0; ks < 4; ks++) {
        uint32_t a[2][4];
#pragma unroll
        for (int mt = 0; mt < 2; mt++)
            ldsm4(a[mt], sa + aoff + (mt * 16 * FPITCH + ks * 16) * 2);
        uint32_t b[8][2];
#pragma unroll
        for (int np = 0; np < 4; np++) {
            uint32_t r[4];
            ldsm4(r, sb + boff + (np * 16 * FPITCH + ks * 16) * 2);
            b[2 * np][0] = r[0]; b[2 * np][1] = r[1];
            b[2 * np + 1][0] = r[2]; b[2 * np + 1][1] = r[3];
        }
#pragma unroll
        for (int mt = 0; mt < 2; mt++)
#pragma unroll
            for (int nt = 0; nt < 8; nt++) {
                if (SKIPG >= 0 && (nt & 3) == SKIPG) continue;
                mma_f16(d[mt][nt], a[mt], b[nt]);
            }
    }
}

// GRU epilogue; fp16 hprev; Sg optional; optional fp32 h out; optional fused group-sum.
__device__ __forceinline__ void gru_epilogue(
    float (&d)[2][8][4], const __half* hp16,
    const float* Sg, float* h32out, __half* h16out,
    __half* Ssum, float* smf,
    int row0, int col0, int wm, int wn, int gq, int tig, int tid)
{
    const float* gb = g_gb;
    const int J0 = col0 >> 2;
#pragma unroll
    for (int a2 = 0; a2 < 2; a2++) {
        const int J = J0 + wn * 16 + a2 * 8 + 2 * tig;
        const float bR0 = gb[J],       bR1 = gb[J + 1];
        const float bZ0 = gb[256 + J], bZ1 = gb[256 + J + 1];
        const float bI0 = gb[512 + J], bI1 = gb[512 + J + 1];
        const float bH0 = gb[768 + J], bH1 = gb[768 + J + 1];
#pragma unroll
        for (int mt = 0; mt < 2; mt++) {
            const int rowa = row0 + wm * 32 + mt * 16 + gq;
#pragma unroll
            for (int half = 0; half < 2; half++) {
                const int row = rowa + half * 8;
                const int e0 = half * 2, e1 = half * 2 + 1;
                float sRx = 0.f, sRy = 0.f, sZx = 0.f, sZy = 0.f, sIx = 0.f, sIy = 0.f;
                if (Sg) {
                    const float* sgr = Sg + (size_t)(row >> 4) * 768 + J;
                    float2 t;
                    t = *(const float2*)(sgr);        sRx = t.x; sRy = t.y;
                    t = *(const float2*)(sgr + 256);  sZx = t.x; sZy = t.y;
                    t = *(const float2*)(sgr + 512);  sIx = t.x; sIy = t.y;
                }
                float r0 = sigf(d[mt][4 * a2 + 0][e0] + sRx + bR0);
                float r1 = sigf(d[mt][4 * a2 + 0][e1] + sRy + bR1);
                float z0 = sigf(d[mt][4 * a2 + 1][e0] + sZx + bZ0);
                float z1 = sigf(d[mt][4 * a2 + 1][e1] + sZy + bZ1);
                float n0 = tanhfast(d[mt][4 * a2 + 2][e0] + sIx + bI0 + r0 * (d[mt][4 * a2 + 3][e0] + bH0));
                float n1 = tanhfast(d[mt][4 * a2 + 2][e1] + sIy + bI1 + r1 * (d[mt][4 * a2 + 3][e1] + bH1));
                float2 hp = __half22float2(*(const __half2*)(hp16 + (size_t)row * HID + J));
                float h0 = (1.0f - z0) * n0 + z0 * hp.x;
                float h1 = (1.0f - z1) * n1 + z1 * hp.y;
                if (h32out) *(float2*)(h32out + (size_t)row * HID + J) = make_float2(h0, h1);
                *(__half2*)(h16out + (size_t)row * HID + J) = __floats2half2_rn(h0, h1);
                if (Ssum) {
                    const int lr = row - row0, lc = J - J0;
                    smf[lr * 33 + lc]     = h0;
                    smf[lr * 33 + lc + 1] = h1;
                }
            }
        }
    }
    if (Ssum) {
        __syncthreads();
        const int g = tid >> 5, c = tid & 31;
        float s = 0.f;
#pragma unroll
        for (int i = 0; i < 16; i++)
            s += smf[(g * 16 + i) * 33 + c];
        Ssum[(size_t)((row0 >> 4) + g) * HID + J0 + c] = __float2half_rn(s);
    }
}

#define FRAG_OFFSETS                                                            \
    const int rA = (lid & 7) + ((lid >> 3) & 1) * 8, kA = ((lid >> 4) & 1) * 8; \
    const int rB = (lid & 7) + ((lid >> 4) & 1) * 8, kB = ((lid >> 3) & 1) * 8; \
    const uint32_t aoff = ((wm * 32 + rA) * FPITCH + kA) * 2;                   \
    const uint32_t boff = ((wn * 64 + rB) * FPITCH + kB) * 2;

#define ACC_INIT                                                                \
    float d[2][8][4];                                                           \
    _Pragma("unroll")                                                           \
    for (int mt = 0; mt < 2; mt++)                                              \
        _Pragma("unroll")                                                       \
        for (int nt = 0; nt < 8; nt++)                                          \
            _Pragma("unroll")                                                   \
            for (int e = 0; e < 4; e++) d[mt][nt][e] = 0.0f;

// ---- cell 1: A = [x | h] (K=512), gate-skip per phase; fused group-sum ----
__global__ __launch_bounds__(256, 2)
void fused_gru(const __half* __restrict__ Ax, const __half* __restrict__ Ah,
               const __half* __restrict__ hp16, __half* __restrict__ h16out,
               __half* __restrict__ Ssum)
{
    extern __shared__ __half sm[];
    const uint32_t s0 = (uint32_t)__cvta_generic_to_shared(sm);
    const uint32_t sB0 = s0 + 2 * FCHUNK * 2;
    const int tid = threadIdx.x, wid = tid >> 5, lid = tid & 31;
    const int wm = wid & 3, wn = wid >> 2;
    const int gq = lid >> 2, tig = lid & 3;
    const int row0 = blockIdx.y * 128, col0 = blockIdx.x * 128;
    FRAG_OFFSETS
    ACC_INIT

#define LD1(kc) do {                                                            \
        uint32_t ba_ = s0 + ((kc) & 1) * FCHUNK * 2;                            \
        uint32_t bb_ = sB0 + ((kc) & 1) * FCHUNK * 2;                           \
        const __half* as_ = ((kc) < 4) ? Ax + (size_t)row0 * HID + (kc) * 64    \
                                       : Ah + (size_t)row0 * HID + ((kc)-4)*64; \
        _Pragma("unroll")                                                       \
        for (int i_ = 0; i_ < 4; i_++) {                                        \
            int idx_ = tid + i_ * 256;                                          \
            int r_ = idx_ >> 3, q_ = idx_ & 7;                                  \
            cpa16(ba_ + (r_ * FPITCH + q_ * 8) * 2, as_ + (size_t)r_ * HID + q_ * 8); \
            cpa16(bb_ + (r_ * FPITCH + q_ * 8) * 2,                             \
                  g_wf + (size_t)(col0 + r_) * 512 + (kc) * 64 + q_ * 8);       \
        }                                                                       \
        asm volatile("cp.async.commit_group;");                                 \
    } while (0)

    LD1(0);
#pragma unroll
    for (int kc = 0; kc < 8; kc++) {
        if (kc + 1 < 8) { LD1(kc + 1); asm volatile("cp.async.wait_group 1;"); }
        else            { asm volatile("cp.async.wait_group 0;"); }
        __syncthreads();
        uint32_t ba = s0 + (kc & 1) * FCHUNK * 2;
        uint32_t bb = sB0 + (kc & 1) * FCHUNK * 2;
        if (kc < 4) compute_chunk<3>(ba, bb, d, aoff, boff);
        else        compute_chunk<2>(ba, bb, d, aoff, boff);
        __syncthreads();
    }
#undef LD1
    gru_epilogue(d, hp16, nullptr, nullptr, h16out, Ssum, (float*)sm,
                 row0, col0, wm, wn, gq, tig, tid);
}

// ---- cells 2/3: gates = h @ Wf2 + Sg[row/16] + bias (K=256); optional fused sum ----
__global__ __launch_bounds__(256, 2)
void fused_gru2(const __half* __restrict__ Ah, const __half* __restrict__ hp16,
                const float* __restrict__ Sg,
                float* __restrict__ h32out, __half* __restrict__ h16out,
                __half* __restrict__ Ssum)
{
    extern __shared__ __half sm[];
    const uint32_t s0 = (uint32_t)__cvta_generic_to_shared(sm);
    const uint32_t sB0 = s0 + 2 * FCHUNK * 2;
    const int tid = threadIdx.x, wid = tid >> 5, lid = tid & 31;
    const int wm = wid & 3, wn = wid >> 2;
    const int gq = lid >> 2, tig = lid & 3;
    const int row0 = blockIdx.y * 128, col0 = blockIdx.x * 128;
    FRAG_OFFSETS
    ACC_INIT

#define LD2(kc) do {                                                            \
        uint32_t ba_ = s0 + ((kc) & 1) * FCHUNK * 2;                            \
        uint32_t bb_ = sB0 + ((kc) & 1) * FCHUNK * 2;                           \
        _Pragma("unroll")                                                       \
        for (int i_ = 0; i_ < 4; i_++) {                                        \
            int idx_ = tid + i_ * 256;                                          \
            int r_ = idx_ >> 3, q_ = idx_ & 7;                                  \
            cpa16(ba_ + (r_ * FPITCH + q_ * 8) * 2,                             \
                  Ah + (size_t)(row0 + r_) * HID + (kc) * 64 + q_ * 8);         \
            cpa16(bb_ + (r_ * FPITCH + q_ * 8) * 2,                             \
                  g_wf2 + (size_t)(col0 + r_) * 256 + (kc) * 64 + q_ * 8);      \
        }                                                                       \
        asm volatile("cp.async.commit_group;");                                 \
    } while (0)

    LD2(0);
#pragma unroll
    for (int kc = 0; kc < 4; kc++) {
        if (kc + 1 < 4) { LD2(kc + 1); asm volatile("cp.async.wait_group 1;"); }
        else            { asm volatile("cp.async.wait_group 0;"); }
        __syncthreads();
        uint32_t ba = s0 + (kc & 1) * FCHUNK * 2;
        uint32_t bb = sB0 + (kc & 1) * FCHUNK * 2;
        compute_chunk<-1>(ba, bb, d, aoff, boff);
        __syncthreads();
    }
#undef LD2
    gru_epilogue(d, hp16, Sg, h32out, h16out, Ssum, (float*)sm,
                 row0, col0, wm, wn, gq, tig, tid);
}

// ---- encoder: 2 row-tiles per CTA, B (encW slice) resident; K=128 ----
__global__ __launch_bounds__(256, 2)
void enc2(const __half* __restrict__ A, const float* __restrict__ bias,
          __half* __restrict__ C16)
{
    extern __shared__ __half sm[];
    const uint32_t s0 = (uint32_t)__cvta_generic_to_shared(sm);
    const uint32_t sB0 = s0 + 2 * FCHUNK * 2;
    const int tid = threadIdx.x, wid = tid >> 5, lid = tid & 31;
    const int wm = wid & 3, wn = wid >> 2;
    const int gq = lid >> 2, tig = lid & 3;
    const int col0 = blockIdx.x * 128;
    FRAG_OFFSETS

    {
#pragma unroll
        for (int kc = 0; kc < 2; kc++) {
            uint32_t bb_ = sB0 + kc * FCHUNK * 2;
#pragma unroll
            for (int i_ = 0; i_ < 4; i_++) {
                int idx_ = tid + i_ * 256;
                int r_ = idx_ >> 3, q_ = idx_ & 7;
                cpa16(bb_ + (r_ * FPITCH + q_ * 8) * 2,
                      g_encw + (size_t)(col0 + r_) * OBS_DIM + kc * 64 + q_ * 8);
            }
        }
        asm volatile("cp.async.commit_group;");
    }

#define LDA_(it) do {                                                           \
        uint32_t ba_ = s0 + ((it) & 1) * FCHUNK * 2;                            \
        int r0_ = blockIdx.y * 256 + ((it) >> 1) * 128;                         \
        _Pragma("unroll")                                                       \
        for (int i_ = 0; i_ < 4; i_++) {                                        \
            int idx_ = tid + i_ * 256;                                          \
            int r_ = idx_ >> 3, q_ = idx_ & 7;                                  \
            cpa16(ba_ + (r_ * FPITCH + q_ * 8) * 2,                             \
                  A + (size_t)(r0_ + r_) * OBS_DIM + ((it) & 1) * 64 + q_ * 8); \
        }                                                                       \
        asm volatile("cp.async.commit_group;");                                 \
    } while (0)

    LDA_(0);
    ACC_INIT
#pragma unroll
    for (int it = 0; it < 4; it++) {
        if (it + 1 < 4) { LDA_(it + 1); asm volatile("cp.async.wait_group 1;"); }
        else            { asm volatile("cp.async.wait_group 0;"); }
        __syncthreads();
        uint32_t ba = s0 + (it & 1) * FCHUNK * 2;
        uint32_t bb = sB0 + (it & 1) * FCHUNK * 2;
        compute_chunk<-1>(ba, bb, d, aoff, boff);
        __syncthreads();

        if (it & 1) {
            int row0 = blockIdx.y * 256 + (it >> 1) * 128;
#pragma unroll
            for (int nt = 0; nt < 8; nt++) {
                int col = col0 + wn * 64 + nt * 8 + 2 * tig;
                float b0 = bias[col], b1 = bias[col + 1];
#pragma unroll
                for (int mt = 0; mt < 2; mt++) {
                    int rowa = row0 + wm * 32 + mt * 16 + gq;
#pragma unroll
                    for (int half = 0; half < 2; half++) {
                        int row = rowa + half * 8;
                        float v0 = sigf(d[mt][nt][half * 2]     + b0);
                        float v1 = sigf(d[mt][nt][half * 2 + 1] + b1);
                        *(__half2*)(C16 + (size_t)row * HID + col) = __floats2half2_rn(v0, v1);
                    }
                }
            }
            if (it == 1) {
#pragma unroll
                for (int mt = 0; mt < 2; mt++)
#pragma unroll
                    for (int nt = 0; nt < 8; nt++)
#pragma unroll
                        for (int e = 0; e < 4; e++) d[mt][nt][e] = 0.0f;
            }
        }
    }
#undef LDA_
}

// ---- Sg GEMM: CTA 64x128, 4 warps @ 32x64, 128 threads, K=256, N=768 exact ----
#define SGA_BYTES (64 * FPITCH * 2)
#define SGB_BYTES (128 * FPITCH * 2)
#define SG_SMEM (2 * (SGA_BYTES + SGB_BYTES))

__global__ __launch_bounds__(128, 4)
void hgemm64(const __half* __restrict__ A, const __half* __restrict__ W,
             float* __restrict__ C32)
{
    extern __shared__ __half sm[];
    const uint32_t s0 = (uint32_t)__cvta_generic_to_shared(sm);
    const uint32_t sB0 = s0 + 2 * SGA_BYTES;
    const int tid = threadIdx.x, wid = tid >> 5, lid = tid & 31;
    const int wm = wid & 1, wn = wid >> 1;
    const int gq = lid >> 2, tig = lid & 3;
    const int row0 = blockIdx.y * 64, col0 = blockIdx.x * 128;
    FRAG_OFFSETS
    ACC_INIT

#define LDS_(kc) do {                                                           \
        uint32_t ba_ = s0 + ((kc) & 1) * SGA_BYTES;                             \
        uint32_t bb_ = sB0 + ((kc) & 1) * SGB_BYTES;                            \
        _Pragma("unroll")                                                       \
        for (int i_ = 0; i_ < 4; i_++) {                                        \
            int idx_ = tid + i_ * 128;                                          \
            int r_ = idx_ >> 3, q_ = idx_ & 7;                                  \
            cpa16(ba_ + (r_ * FPITCH + q_ * 8) * 2,                             \
                  A + (size_t)(row0 + r_) * HID + (kc) * 64 + q_ * 8);          \
        }                                                                       \
        _Pragma("unroll")                                                       \
        for (int i_ = 0; i_ < 8; i_++) {                                        \
            int idx_ = tid + i_ * 128;                                          \
            int r_ = idx_ >> 3, q_ = idx_ & 7;                                  \
            cpa16(bb_ + (r_ * FPITCH + q_ * 8) * 2,                             \
                  W + (size_t)(col0 + r_) * HID + (kc) * 64 + q_ * 8);          \
        }                                                                       \
        asm volatile("cp.async.commit_group;");                                 \
    } while (0)

    LDS_(0);
#pragma unroll
    for (int kc = 0; kc < 4; kc++) {
        if (kc + 1 < 4) { LDS_(kc + 1); asm volatile("cp.async.wait_group 1;"); }
        else            { asm volatile("cp.async.wait_group 0;"); }
        __syncthreads();
        uint32_t ba = s0 + (kc & 1) * SGA_BYTES;
        uint32_t bb = sB0 + (kc & 1) * SGB_BYTES;
        compute_chunk<-1>(ba, bb, d, aoff, boff);
        __syncthreads();
    }
#undef LDS_

#pragma unroll
    for (int nt = 0; nt < 8; nt++) {
        int col = col0 + wn * 64 + nt * 8 + 2 * tig;
#pragma unroll
        for (int mt = 0; mt < 2; mt++) {
            int rowa = row0 + wm * 32 + mt * 16 + gq;
#pragma unroll
            for (int half = 0; half < 2; half++) {
                int row = rowa + half * 8;
                *(float2*)(C32 + (size_t)row * 768 + col) =
                    make_float2(d[mt][nt][half * 2], d[mt][nt][half * 2 + 1]);
            }
        }
    }
}

// ---- decoder GEMM: CTA 256x32, 8 warps (32 rows x 32 cols each), K=256 ----
#define DA_BYTES (256 * FPITCH * 2)
#define DB_BYTES (32 * FPITCH * 2)
#define DEC_SMEM (2 * (DA_BYTES + DB_BYTES))

__global__ __launch_bounds__(256, 2)
void dec_gemm(const __half* __restrict__ A, const float* __restrict__ bias,
              float* __restrict__ C)
{
    extern __shared__ __half sm[];
    const uint32_t s0 = (uint32_t)__cvta_generic_to_shared(sm);
    const uint32_t sB0 = s0 + 2 * DA_BYTES;
    const int tid = threadIdx.x, wid = tid >> 5, lid = tid & 31;
    const int gq = lid >> 2, tig = lid & 3;
    const int row0 = blockIdx.y * 256;
    const int rA = (lid & 7) + ((lid >> 3) & 1) * 8, kA = ((lid >> 4) & 1) * 8;
    const int rB = (lid & 7) + ((lid >> 4) & 1) * 8, kB = ((lid >> 3) & 1) * 8;
    const uint32_t aoff = ((wid * 32 + rA) * FPITCH + kA) * 2;
    const uint32_t boff = (rB * FPITCH + kB) * 2;

    float d[2][4][4];
#pragma unroll
    for (int mt = 0; mt < 2; mt++)
#pragma unroll
        for (int nt = 0; nt < 4; nt++)
#pragma unroll
            for (int e = 0; e < 4; e++) d[mt][nt][e] = 0.0f;

#define LDD_(kc) do {                                                           \
        uint32_t ba_ = s0 + ((kc) & 1) * DA_BYTES;                              \
        uint32_t bb_ = sB0 + ((kc) & 1) * DB_BYTES;                             \
        _Pragma("unroll")                                                       \
        for (int i_ = 0; i_ < 8; i_++) {                                        \
            int idx_ = tid + i_ * 256;                                          \
            int r_ = idx_ >> 3, q_ = idx_ & 7;                                  \
            cpa16(ba_ + (r_ * FPITCH + q_ * 8) * 2,                             \
                  A + (size_t)(row0 + r_) * HID + (kc) * 64 + q_ * 8);          \
        }                                                                       \
        { int r_ = tid >> 3, q_ = tid & 7;                                      \
          cpa16(bb_ + (r_ * FPITCH + q_ * 8) * 2,                               \
                g_decw + (size_t)r_ * HID + (kc) * 64 + q_ * 8); }              \
        asm volatile("cp.async.commit_group;");                                 \
    } while (0)

    LDD_(0);
#pragma unroll
    for (int kc = 0; kc < 4; kc++) {
        if (kc + 1 < 4) { LDD_(kc + 1); asm volatile("cp.async.wait_group 1;"); }
        else            { asm volatile("cp.async.wait_group 0;"); }
        __syncthreads();
        uint32_t ba = s0 + (kc & 1) * DA_BYTES;
        uint32_t bb = sB0 + (kc & 1) * DB_BYTES;
#pragma unroll
        for (int ks = 0; ks < 4; ks++) {
            uint32_t a[2][4];
#pragma unroll
            for (int mt = 0; mt < 2; mt++)
                ldsm4(a[mt], ba + aoff + (mt * 16 * FPITCH + ks * 16) * 2);
            uint32_t b[4][2];
#pragma unroll
            for (int np = 0; np < 2; np++) {
                uint32_t r[4];
                ldsm4(r, bb + boff + (np * 16 * FPITCH + ks * 16) * 2);
                b[2 * np][0] = r[0]; b[2 * np][1] = r[1];
                b[2 * np + 1][0] = r[2]; b[2 * np + 1][1] = r[3];
            }
#pragma unroll
            for (int mt = 0; mt < 2; mt++)
#pragma unroll
                for (int nt = 0; nt < 4; nt++)
                    mma_f16(d[mt][nt], a[mt], b[nt]);
        }
        __syncthreads();
    }
#undef LDD_

#pragma unroll
    for (int nt = 0; nt < 4; nt++) {
        int col = nt * 8 + 2 * tig;
        float b0 = bias[col], b1 = bias[col + 1];
#pragma unroll
        for (int mt = 0; mt < 2; mt++) {
            int rowa = row0 + wid * 32 + mt * 16 + gq;
#pragma unroll
            for (int half = 0; half < 2; half++) {
                int row = rowa + half * 8;
                *(float2*)(C + (size_t)row * N_ACTIONS + col) =
                    make_float2(d[mt][nt][half * 2] + b0, d[mt][nt][half * 2 + 1] + b1);
            }
        }
    }
}

// ================= split prep kernels =================
#define N_OBS4 (ROWS * OBS_DIM / 4)
#define N_H04  (ROWS * HID / 4)
#define PREP_MAIN_TOTAL (N_OBS4 + 32768)
#define PREP_REST_TOTAL (N_H04 + 524288 + 262144 + 196608 + 8192 + 1024)

__global__ void prep_main(const float* __restrict__ obs, const float* __restrict__ enc_w)
{
    int idx = blockIdx.x * blockDim.x + threadIdx.x;
    if (idx < N_OBS4) {
        float4 v = ((const float4*)obs)[idx];
        ((__half2*)g_obs16)[2 * idx]     = __floats2half2_rn(v.x, v.y);
        ((__half2*)g_obs16)[2 * idx + 1] = __floats2half2_rn(v.z, v.w);
        return;
    }
    idx -= N_OBS4;
    if (idx < 32768) g_encw[idx] = __float2half_rn(enc_w[idx]);
}

__global__ void prep_rest(const float* __restrict__ h0,
                          const float* __restrict__ w_ih, const float* __restrict__ w_hh,
                          const float* __restrict__ b_ih, const float* __restrict__ b_hh,
                          const float* __restrict__ dec_w)
{
    int idx = blockIdx.x * blockDim.x + threadIdx.x;
    const float inv = 1.0f / (float)N_AGENTS;
    if (idx < N_H04) {
        float4 v = ((const float4*)h0)[idx];
        ((__half2*)g_h016)[2 * idx]     = __floats2half2_rn(v.x, v.y);
        ((__half2*)g_h016)[2 * idx + 1] = __floats2half2_rn(v.z, v.w);
        return;
    }
    idx -= N_H04;
    if (idx < 524288) {
        int c = idx >> 9, k = idx & 511;
        int g = (c >> 3) & 3;
        int j = ((c >> 5) << 3) + (c & 7);
        float v;
        if (g == 0)      v = (k < 256) ? w_ih[j * 256 + k]         : w_hh[j * 256 + k - 256];
        else if (g == 1) v = (k < 256) ? w_ih[(256 + j) * 256 + k] : w_hh[(256 + j) * 256 + k - 256];
        else if (g == 2) v = (k < 256) ? w_ih[(512 + j) * 256 + k] : 0.0f;
        else             v = (k < 256) ? 0.0f                      : w_hh[(512 + j) * 256 + k - 256];
        g_wf[c * 512 + k] = __float2half_rn(v);
        return;
    }
    idx -= 524288;
    if (idx < 262144) {
        int c = idx >> 8, k = idx & 255;
        int g = (c >> 3) & 3;
        int j = ((c >> 5) << 3) + (c & 7);
        float v;
        if (g == 0)      v = w_hh[j * 256 + k]         - w_ih[j * 256 + k] * inv;
        else if (g == 1) v = w_hh[(256 + j) * 256 + k] - w_ih[(256 + j) * 256 + k] * inv;
        else if (g == 2) v = -w_ih[(512 + j) * 256 + k] * inv;
        else             v = w_hh[(512 + j) * 256 + k];
        g_wf2[c * 256 + k] = __float2half_rn(v);
        return;
    }
    idx -= 262144;
    if (idx < 196608) { g_ws16[idx] = __float2half_rn(w_ih[idx] * inv); return; }
    idx -= 196608;
    if (idx < 8192)   { g_decw[idx] = __float2half_rn(dec_w[idx]); return; }
    idx -= 8192;
    if (idx < 1024) {
        int g = idx >> 8, j = idx & 255;
        float v;
        if (g == 0)      v = b_ih[j] + b_hh[j];
        else if (g == 1) v = b_ih[256 + j] + b_hh[256 + j];
        else if (g == 2) v = b_ih[512 + j];
        else             v = b_hh[512 + j];
        g_gb[idx] = v;
    }
}

extern "C" void kernel_launch(void* const* d_in, const int* in_sizes, int n_in,
                              void* d_out, int out_size)
{
    const float* obs   = (const float*)d_in[0];
    const float* h0    = (const float*)d_in[1];
    const float* enc_w = (const float*)d_in[2];
    const float* enc_b = (const float*)d_in[3];
    const float* w_ih  = (const float*)d_in[4];
    const float* w_hh  = (const float*)d_in[5];
    const float* b_ih  = (const float*)d_in[6];
    const float* b_hh  = (const float*)d_in[7];
    const float* dec_w = (const float*)d_in[8];
    const float* dec_b = (const float*)d_in[9];
    float* out = (float*)d_out;

    __half *x16, *h16a, *h16b, *obs16, *h016, *ws16, *S16;
    float *Sg;
    cudaGetSymbolAddress((void**)&x16,   g_x16);
    cudaGetSymbolAddress((void**)&h16a,  g_h16a);
    cudaGetSymbolAddress((void**)&h16b,  g_h16b);
    cudaGetSymbolAddress((void**)&obs16, g_obs16);
    cudaGetSymbolAddress((void**)&h016,  g_h016);
    cudaGetSymbolAddress((void**)&ws16,  g_ws16);
    cudaGetSymbolAddress((void**)&S16,   g_S16);
    cudaGetSymbolAddress((void**)&Sg,    g_Sg);

    cudaFuncSetAttribute(fused_gru,  cudaFuncAttributeMaxDynamicSharedMemorySize, FSMEM_BYTES);
    cudaFuncSetAttribute(fused_gru2, cudaFuncAttributeMaxDynamicSharedMemorySize, FSMEM_BYTES);
    cudaFuncSetAttribute(enc2,       cudaFuncAttributeMaxDynamicSharedMemorySize, FSMEM_BYTES);
    cudaFuncSetAttribute(hgemm64,    cudaFuncAttributeMaxDynamicSharedMemorySize, SG_SMEM);
    cudaFuncSetAttribute(dec_gemm,   cudaFuncAttributeMaxDynamicSharedMemorySize, DEC_SMEM);

    dim3 t(256);

    cudaStream_t s2;
    cudaEvent_t evFork, evJoin;
    cudaStreamCreateWithFlags(&s2, cudaStreamNonBlocking);
    cudaEventCreateWithFlags(&evFork, cudaEventDisableTiming);
    cudaEventCreateWithFlags(&evJoin, cudaEventDisableTiming);

    cudaEventRecord(evFork, 0);
    cudaStreamWaitEvent(s2, evFork, 0);
    prep_rest<<<(PREP_REST_TOTAL + 255) / 256, 256, 0, s2>>>(h0, w_ih, w_hh, b_ih, b_hh, dec_w);
    cudaEventRecord(evJoin, s2);

    prep_main<<<(PREP_MAIN_TOTAL + 255) / 256, 256>>>(obs, enc_w);
    enc2<<<dim3(2, ROWS / 256), t, FSMEM_BYTES>>>(obs16, enc_b, x16);

    cudaStreamWaitEvent(0, evJoin, 0);

    // cell 1 (fp16 hprev = h016), fused group-sum -> S16
    fused_gru<<<dim3(8, ROWS / 128), t, FSMEM_BYTES>>>(x16, h016, h016, h16a, S16);

    // comm 1 GEMM + cell 2 (fused sum -> S16 for comm 2)
    hgemm64<<<dim3(6, NGROUP / 64), 128, SG_SMEM>>>(S16, ws16, Sg);
    fused_gru2<<<dim3(8, ROWS / 128), t, FSMEM_BYTES>>>(h16a, h16a, Sg, nullptr, h16b, S16);

    // comm 2 GEMM + cell 3 (fp32 h straight into d_out tail, no sum)
    hgemm64<<<dim3(6, NGROUP / 64), 128, SG_SMEM>>>(S16, ws16, Sg);
    fused_gru2<<<dim3(8, ROWS / 128), t, FSMEM_BYTES>>>(h16b, h16b, Sg,
                                                        out + (size_t)ROWS * N_ACTIONS, h16a, nullptr);

    // decoder (dedicated N=32 kernel)
    dec_gemm<<<dim3(1, ROWS / 256), t, DEC_SMEM>>>(h16a, dec_b, out);

    cudaEventDestroy(evFork);
    cudaEventDestroy(evJoin);
    cudaStreamDestroy(s2);
}

// round 16
// speedup vs baseline: 1.0632x; 1.0025x over previous
#include <cuda_runtime.h>
#include <cuda_fp16.h>
#include <math.h>
#include <stdint.h>

#define ROWS 131072
#define HID 256
#define OBS_DIM 128
#define N_ACTIONS 32
#define N_AGENTS 16
#define NGROUP (ROWS / N_AGENTS)

// -------- scratch --------
__device__ __half g_x16 [ROWS * HID];
__device__ __half g_h16a[ROWS * HID];
__device__ __half g_h16b[ROWS * HID];
__device__ __half g_obs16[ROWS * OBS_DIM];
__device__ __half g_h016[ROWS * HID];
__device__ __half g_wf  [1024 * 512];
__device__ __half g_wf2 [1024 * 256];
__device__ __half g_ws16[768 * 256];
__device__ float  g_gb  [1024];
__device__ __half g_S16 [NGROUP * HID];
__device__ float  g_Sg  [NGROUP * 768];
__device__ __half g_encw[HID * OBS_DIM];
__device__ __half g_decw[N_ACTIONS * HID];

// ===== geometry: CTA 128x128, 8 warps @ 32x64, K-chunk 64, double buffer =====
#define FPITCH 72
#define FCHUNK (128 * FPITCH)
#define FSMEM_BYTES (4 * FCHUNK * 2)     /* 73728 B -> 2 CTAs/SM */

__device__ __forceinline__ void mma_f16(float* d, const uint32_t* a, const uint32_t* b) {
    asm volatile(
        "mma.sync.aligned.m16n8k16.row.col.f32.f16.f16.f32 "
        "{%0,%1,%2,%3}, {%4,%5,%6,%7}, {%8,%9}, {%0,%1,%2,%3};"
        : "+f"(d[0]), "+f"(d[1]), "+f"(d[2]), "+f"(d[3])
        : "r"(a[0]), "r"(a[1]), "r"(a[2]), "r"(a[3]), "r"(b[0]), "r"(b[1]));
}
__device__ __forceinline__ void ldsm4(uint32_t* r, uint32_t addr) {
    asm volatile("ldmatrix.sync.aligned.m8n8.x4.shared.b16 {%0,%1,%2,%3}, [%4];"
        : "=r"(r[0]), "=r"(r[1]), "=r"(r[2]), "=r"(r[3]) : "r"(addr));
}
__device__ __forceinline__ float sigf(float u) {
    float e = __expf(-u);
    return __fdividef(1.0f, 1.0f + e);
}
__device__ __forceinline__ float tanhfast(float t) {
    float e = __expf(-2.0f * fabsf(t));
    return copysignf(__fdividef(1.0f - e, 1.0f + e), t);
}
__device__ __forceinline__ void cpa16(uint32_t dst, const void* src) {
    asm volatile("cp.async.cg.shared.global [%0], [%1], 16;" :: "r"(dst), "l"(src));
}

// one K=64 chunk via ldmatrix; SKIPG = gate col (nt&3) to skip, or -1
template<int SKIPG>
__device__ __forceinline__ void compute_chunk(uint32_t sa, uint32_t sb,
                                              float (&d)[2][8][4],
                                              uint32_t aoff, uint32_t boff)
{
#pragma unroll
    for (int ks = 0; ks < 4; ks++) {
        uint32_t a[2][4];
#pragma unroll
        for (int mt = 0; mt < 2; mt++)
            ldsm4(a[mt], sa + aoff + (mt * 16 * FPITCH + ks * 16) * 2);
        uint32_t b[8][2];
#pragma unroll
        for (int np = 0; np < 4; np++) {
            uint32_t r[4];
            ldsm4(r, sb + boff + (np * 16 * FPITCH + ks * 16) * 2);
            b[2 * np][0] = r[0]; b[2 * np][1] = r[1];
            b[2 * np + 1][0] = r[2]; b[2 * np + 1][1] = r[3];
        }
#pragma unroll
        for (int mt = 0; mt < 2; mt++)
#pragma unroll
            for (int nt = 0; nt < 8; nt++) {
                if (SKIPG >= 0 && (nt & 3) == SKIPG) continue;
                mma_f16(d[mt][nt], a[mt], b[nt]);
            }
    }
}

// GRU epilogue; fp16 hprev; Sg optional; optional fp32 h out; optional fused group-sum.
__device__ __forceinline__ void gru_epilogue(
    float (&d)[2][8][4], const __half* hp16,
    const float* Sg, float* h32out, __half* h16out,
    __half* Ssum, float* smf,
    int row0, int col0, int wm, int wn, int gq, int tig, int tid)
{
    const float* gb = g_gb;
    const int J0 = col0 >> 2;
#pragma unroll
    for (int a2 = 0; a2 < 2; a2++) {
        const int J = J0 + wn * 16 + a2 * 8 + 2 * tig;
        const float bR0 = gb[J],       bR1 = gb[J + 1];
        const float bZ0 = gb[256 + J], bZ1 = gb[256 + J + 1];
        const float bI0 = gb[512 + J], bI1 = gb[512 + J + 1];
        const float bH0 = gb[768 + J], bH1 = gb[768 + J + 1];
#pragma unroll
        for (int mt = 0; mt < 2; mt++) {
            const int rowa = row0 + wm * 32 + mt * 16 + gq;
#pragma unroll
            for (int half = 0; half < 2; half++) {
                const int row = rowa + half * 8;
                const int e0 = half * 2, e1 = half * 2 + 1;
                float sRx = 0.f, sRy = 0.f, sZx = 0.f, sZy = 0.f, sIx = 0.f, sIy = 0.f;
                if (Sg) {
                    const float* sgr = Sg + (size_t)(row >> 4) * 768 + J;
                    float2 t;
                    t = *(const float2*)(sgr);        sRx = t.x; sRy = t.y;
                    t = *(const float2*)(sgr + 256);  sZx = t.x; sZy = t.y;
                    t = *(const float2*)(sgr + 512);  sIx = t.x; sIy = t.y;
                }
                float r0 = sigf(d[mt][4 * a2 + 0][e0] + sRx + bR0);
                float r1 = sigf(d[mt][4 * a2 + 0][e1] + sRy + bR1);
                float z0 = sigf(d[mt][4 * a2 + 1][e0] + sZx + bZ0);
                float z1 = sigf(d[mt][4 * a2 + 1][e1] + sZy + bZ1);
                float n0 = tanhfast(d[mt][4 * a2 + 2][e0] + sIx + bI0 + r0 * (d[mt][4 * a2 + 3][e0] + bH0));
                float n1 = tanhfast(d[mt][4 * a2 + 2][e1] + sIy + bI1 + r1 * (d[mt][4 * a2 + 3][e1] + bH1));
                float2 hp = __half22float2(*(const __half2*)(hp16 + (size_t)row * HID + J));
                float h0 = (1.0f - z0) * n0 + z0 * hp.x;
                float h1 = (1.0f - z1) * n1 + z1 * hp.y;
                if (h32out) *(float2*)(h32out + (size_t)row * HID + J) = make_float2(h0, h1);
                *(__half2*)(h16out + (size_t)row * HID + J) = __floats2half2_rn(h0, h1);
                if (Ssum) {
                    const int lr = row - row0, lc = J - J0;
                    smf[lr * 33 + lc]     = h0;
                    smf[lr * 33 + lc + 1] = h1;
                }
            }
        }
    }
    if (Ssum) {
        __syncthreads();
        const int g = tid >> 5, c = tid & 31;
        float s = 0.f;
#pragma unroll
        for (int i = 0; i < 16; i++)
            s += smf[(g * 16 + i) * 33 + c];
        Ssum[(size_t)((row0 >> 4) + g) * HID + J0 + c] = __float2half_rn(s);
    }
}

#define FRAG_OFFSETS                                                            \
    const int rA = (lid & 7) + ((lid >> 3) & 1) * 8, kA = ((lid >> 4) & 1) * 8; \
    const int rB = (lid & 7) + ((lid >> 4) & 1) * 8, kB = ((lid >> 3) & 1) * 8; \
    const uint32_t aoff = ((wm * 32 + rA) * FPITCH + kA) * 2;                   \
    const uint32_t boff = ((wn * 64 + rB) * FPITCH + kB) * 2;

#define ACC_INIT                                                                \
    float d[2][8][4];                                                           \
    _Pragma("unroll")                                                           \
    for (int mt = 0; mt < 2; mt++)                                              \
        _Pragma("unroll")                                                       \
        for (int nt = 0; nt < 8; nt++)                                          \
            _Pragma("unroll")                                                   \
            for (int e = 0; e < 4; e++) d[mt][nt][e] = 0.0f;

// ---- cell 1: A = [x | h] (K=512), gate-skip per phase; fused group-sum ----
__global__ __launch_bounds__(256, 2)
void fused_gru(const __half* __restrict__ Ax, const __half* __restrict__ Ah,
               const __half* __restrict__ hp16, __half* __restrict__ h16out,
               __half* __restrict__ Ssum)
{
    extern __shared__ __half sm[];
    const uint32_t s0 = (uint32_t)__cvta_generic_to_shared(sm);
    const uint32_t sB0 = s0 + 2 * FCHUNK * 2;
    const int tid = threadIdx.x, wid = tid >> 5, lid = tid & 31;
    const int wm = wid & 3, wn = wid >> 2;
    const int gq = lid >> 2, tig = lid & 3;
    const int row0 = blockIdx.y * 128, col0 = blockIdx.x * 128;
    FRAG_OFFSETS
    ACC_INIT

#define LD1(kc) do {                                                            \
        uint32_t ba_ = s0 + ((kc) & 1) * FCHUNK * 2;                            \
        uint32_t bb_ = sB0 + ((kc) & 1) * FCHUNK * 2;                           \
        const __half* as_ = ((kc) < 4) ? Ax + (size_t)row0 * HID + (kc) * 64    \
                                       : Ah + (size_t)row0 * HID + ((kc)-4)*64; \
        _Pragma("unroll")                                                       \
        for (int i_ = 0; i_ < 4; i_++) {                                        \
            int idx_ = tid + i_ * 256;                                          \
            int r_ = idx_ >> 3, q_ = idx_ & 7;                                  \
            cpa16(ba_ + (r_ * FPITCH + q_ * 8) * 2, as_ + (size_t)r_ * HID + q_ * 8); \
            cpa16(bb_ + (r_ * FPITCH + q_ * 8) * 2,                             \
                  g_wf + (size_t)(col0 + r_) * 512 + (kc) * 64 + q_ * 8);       \
        }                                                                       \
        asm volatile("cp.async.commit_group;");                                 \
    } while (0)

    LD1(0);
#pragma unroll
    for (int kc = 0; kc < 8; kc++) {
        if (kc + 1 < 8) { LD1(kc + 1); asm volatile("cp.async.wait_group 1;"); }
        else            { asm volatile("cp.async.wait_group 0;"); }
        __syncthreads();
        uint32_t ba = s0 + (kc & 1) * FCHUNK * 2;
        uint32_t bb = sB0 + (kc & 1) * FCHUNK * 2;
        if (kc < 4) compute_chunk<3>(ba, bb, d, aoff, boff);
        else        compute_chunk<2>(ba, bb, d, aoff, boff);
        __syncthreads();
    }
#undef LD1
    gru_epilogue(d, hp16, nullptr, nullptr, h16out, Ssum, (float*)sm,
                 row0, col0, wm, wn, gq, tig, tid);
}

// ---- cells 2/3: gates = h @ Wf2 + Sg[row/16] + bias (K=256); optional fused sum ----
__global__ __launch_bounds__(256, 2)
void fused_gru2(const __half* __restrict__ Ah, const __half* __restrict__ hp16,
                const float* __restrict__ Sg,
                float* __restrict__ h32out, __half* __restrict__ h16out,
                __half* __restrict__ Ssum)
{
    extern __shared__ __half sm[];
    const uint32_t s0 = (uint32_t)__cvta_generic_to_shared(sm);
    const uint32_t sB0 = s0 + 2 * FCHUNK * 2;
    const int tid = threadIdx.x, wid = tid >> 5, lid = tid & 31;
    const int wm = wid & 3, wn = wid >> 2;
    const int gq = lid >> 2, tig = lid & 3;
    const int row0 = blockIdx.y * 128, col0 = blockIdx.x * 128;
    FRAG_OFFSETS
    ACC_INIT

#define LD2(kc) do {                                                            \
        uint32_t ba_ = s0 + ((kc) & 1) * FCHUNK * 2;                            \
        uint32_t bb_ = sB0 + ((kc) & 1) * FCHUNK * 2;                           \
        _Pragma("unroll")                                                       \
        for (int i_ = 0; i_ < 4; i_++) {                                        \
            int idx_ = tid + i_ * 256;                                          \
            int r_ = idx_ >> 3, q_ = idx_ & 7;                                  \
            cpa16(ba_ + (r_ * FPITCH + q_ * 8) * 2,                             \
                  Ah + (size_t)(row0 + r_) * HID + (kc) * 64 + q_ * 8);         \
            cpa16(bb_ + (r_ * FPITCH + q_ * 8) * 2,                             \
                  g_wf2 + (size_t)(col0 + r_) * 256 + (kc) * 64 + q_ * 8);      \
        }                                                                       \
        asm volatile("cp.async.commit_group;");                                 \
    } while (0)

    LD2(0);
#pragma unroll
    for (int kc = 0; kc < 4; kc++) {
        if (kc + 1 < 4) { LD2(kc + 1); asm volatile("cp.async.wait_group 1;"); }
        else            { asm volatile("cp.async.wait_group 0;"); }
        __syncthreads();
        uint32_t ba = s0 + (kc & 1) * FCHUNK * 2;
        uint32_t bb = sB0 + (kc & 1) * FCHUNK * 2;
        compute_chunk<-1>(ba, bb, d, aoff, boff);
        __syncthreads();
    }
#undef LD2
    gru_epilogue(d, hp16, Sg, h32out, h16out, Ssum, (float*)sm,
                 row0, col0, wm, wn, gq, tig, tid);
}

// ---- encoder: 2 row-tiles per CTA, B (encW slice) resident; K=128 ----
__global__ __launch_bounds__(256, 2)
void enc2(const __half* __restrict__ A, const float* __restrict__ bias,
          __half* __restrict__ C16)
{
    extern __shared__ __half sm[];
    const uint32_t s0 = (uint32_t)__cvta_generic_to_shared(sm);
    const uint32_t sB0 = s0 + 2 * FCHUNK * 2;
    const int tid = threadIdx.x, wid = tid >> 5, lid = tid & 31;
    const int wm = wid & 3, wn = wid >> 2;
    const int gq = lid >> 2, tig = lid & 3;
    const int col0 = blockIdx.x * 128;
    FRAG_OFFSETS

    {
#pragma unroll
        for (int kc = 0; kc < 2; kc++) {
            uint32_t bb_ = sB0 + kc * FCHUNK * 2;
#pragma unroll
            for (int i_ = 0; i_ < 4; i_++) {
                int idx_ = tid + i_ * 256;
                int r_ = idx_ >> 3, q_ = idx_ & 7;
                cpa16(bb_ + (r_ * FPITCH + q_ * 8) * 2,
                      g_encw + (size_t)(col0 + r_) * OBS_DIM + kc * 64 + q_ * 8);
            }
        }
        asm volatile("cp.async.commit_group;");
    }

#define LDA_(it) do {                                                           \
        uint32_t ba_ = s0 + ((it) & 1) * FCHUNK * 2;                            \
        int r0_ = blockIdx.y * 256 + ((it) >> 1) * 128;                         \
        _Pragma("unroll")                                                       \
        for (int i_ = 0; i_ < 4; i_++) {                                        \
            int idx_ = tid + i_ * 256;                                          \
            int r_ = idx_ >> 3, q_ = idx_ & 7;                                  \
            cpa16(ba_ + (r_ * FPITCH + q_ * 8) * 2,                             \
                  A + (size_t)(r0_ + r_) * OBS_DIM + ((it) & 1) * 64 + q_ * 8); \
        }                                                                       \
        asm volatile("cp.async.commit_group;");                                 \
    } while (0)

    LDA_(0);
    ACC_INIT
#pragma unroll
    for (int it = 0; it < 4; it++) {
        if (it + 1 < 4) { LDA_(it + 1); asm volatile("cp.async.wait_group 1;"); }
        else            { asm volatile("cp.async.wait_group 0;"); }
        __syncthreads();
        uint32_t ba = s0 + (it & 1) * FCHUNK * 2;
        uint32_t bb = sB0 + (it & 1) * FCHUNK * 2;
        compute_chunk<-1>(ba, bb, d, aoff, boff);
        __syncthreads();

        if (it & 1) {
            int row0 = blockIdx.y * 256 + (it >> 1) * 128;
#pragma unroll
            for (int nt = 0; nt < 8; nt++) {
                int col = col0 + wn * 64 + nt * 8 + 2 * tig;
                float b0 = bias[col], b1 = bias[col + 1];
#pragma unroll
                for (int mt = 0; mt < 2; mt++) {
                    int rowa = row0 + wm * 32 + mt * 16 + gq;
#pragma unroll
                    for (int half = 0; half < 2; half++) {
                        int row = rowa + half * 8;
                        float v0 = sigf(d[mt][nt][half * 2]     + b0);
                        float v1 = sigf(d[mt][nt][half * 2 + 1] + b1);
                        *(__half2*)(C16 + (size_t)row * HID + col) = __floats2half2_rn(v0, v1);
                    }
                }
            }
            if (it == 1) {
#pragma unroll
                for (int mt = 0; mt < 2; mt++)
#pragma unroll
                    for (int nt = 0; nt < 8; nt++)
#pragma unroll
                        for (int e = 0; e < 4; e++) d[mt][nt][e] = 0.0f;
            }
        }
    }
#undef LDA_
}

// ---- Sg GEMM: CTA 64x128, 4 warps @ 32x64, 128 threads, K=256, N=768 exact ----
#define SGA_BYTES (64 * FPITCH * 2)
#define SGB_BYTES (128 * FPITCH * 2)
#define SG_SMEM (2 * (SGA_BYTES + SGB_BYTES))

__global__ __launch_bounds__(128, 4)
void hgemm64(const __half* __restrict__ A, const __half* __restrict__ W,
             float* __restrict__ C32)
{
    extern __shared__ __half sm[];
    const uint32_t s0 = (uint32_t)__cvta_generic_to_shared(sm);
    const uint32_t sB0 = s0 + 2 * SGA_BYTES;
    const int tid = threadIdx.x, wid = tid >> 5, lid = tid & 31;
    const int wm = wid & 1, wn = wid >> 1;
    const int gq = lid >> 2, tig = lid & 3;
    const int row0 = blockIdx.y * 64, col0 = blockIdx.x * 128;
    FRAG_OFFSETS
    ACC_INIT

#define LDS_(kc) do {                                                           \
        uint32_t ba_ = s0 + ((kc) & 1) * SGA_BYTES;                             \
        uint32_t bb_ = sB0 + ((kc) & 1) * SGB_BYTES;                            \
        _Pragma("unroll")                                                       \
        for (int i_ = 0; i_ < 4; i_++) {                                        \
            int idx_ = tid + i_ * 128;                                          \
            int r_ = idx_ >> 3, q_ = idx_ & 7;                                  \
            cpa16(ba_ + (r_ * FPITCH + q_ * 8) * 2,                             \
                  A + (size_t)(row0 + r_) * HID + (kc) * 64 + q_ * 8);          \
        }                                                                       \
        _Pragma("unroll")                                                       \
        for (int i_ = 0; i_ < 8; i_++) {                                        \
            int idx_ = tid + i_ * 128;                                          \
            int r_ = idx_ >> 3, q_ = idx_ & 7;                                  \
            cpa16(bb_ + (r_ * FPITCH + q_ * 8) * 2,                             \
                  W + (size_t)(col0 + r_) * HID + (kc) * 64 + q_ * 8);          \
        }                                                                       \
        asm volatile("cp.async.commit_group;");                                 \
    } while (0)

    LDS_(0);
#pragma unroll
    for (int kc = 0; kc < 4; kc++) {
        if (kc + 1 < 4) { LDS_(kc + 1); asm volatile("cp.async.wait_group 1;"); }
        else            { asm volatile("cp.async.wait_group 0;"); }
        __syncthreads();
        uint32_t ba = s0 + (kc & 1) * SGA_BYTES;
        uint32_t bb = sB0 + (kc & 1) * SGB_BYTES;
        compute_chunk<-1>(ba, bb, d, aoff, boff);
        __syncthreads();
    }
#undef LDS_

#pragma unroll
    for (int nt = 0; nt < 8; nt++) {
        int col = col0 + wn * 64 + nt * 8 + 2 * tig;
#pragma unroll
        for (int mt = 0; mt < 2; mt++) {
            int rowa = row0 + wm * 32 + mt * 16 + gq;
#pragma unroll
            for (int half = 0; half < 2; half++) {
                int row = rowa + half * 8;
                *(float2*)(C32 + (size_t)row * 768 + col) =
                    make_float2(d[mt][nt][half * 2], d[mt][nt][half * 2 + 1]);
            }
        }
    }
}

// ---- decoder GEMM: CTA 256x32, 8 warps (32 rows x 32 cols each), K=256 ----
#define DA_BYTES (256 * FPITCH * 2)
#define DB_BYTES (32 * FPITCH * 2)
#define DEC_SMEM (2 * (DA_BYTES + DB_BYTES))

__global__ __launch_bounds__(256, 2)
void dec_gemm(const __half* __restrict__ A, const float* __restrict__ bias,
              float* __restrict__ C)
{
    extern __shared__ __half sm[];
    const uint32_t s0 = (uint32_t)__cvta_generic_to_shared(sm);
    const uint32_t sB0 = s0 + 2 * DA_BYTES;
    const int tid = threadIdx.x, wid = tid >> 5, lid = tid & 31;
    const int gq = lid >> 2, tig = lid & 3;
    const int row0 = blockIdx.y * 256;
    const int rA = (lid & 7) + ((lid >> 3) & 1) * 8, kA = ((lid >> 4) & 1) * 8;
    const int rB = (lid & 7) + ((lid >> 4) & 1) * 8, kB = ((lid >> 3) & 1) * 8;
    const uint32_t aoff = ((wid * 32 + rA) * FPITCH + kA) * 2;
    const uint32_t boff = (rB * FPITCH + kB) * 2;

    float d[2][4][4];
#pragma unroll
    for (int mt = 0; mt < 2; mt++)
#pragma unroll
        for (int nt = 0; nt < 4; nt++)
#pragma unroll
            for (int e = 0; e < 4; e++) d[mt][nt][e] = 0.0f;

#define LDD_(kc) do {                                                           \
        uint32_t ba_ = s0 + ((kc) & 1) * DA_BYTES;                              \
        uint32_t bb_ = sB0 + ((kc) & 1) * DB_BYTES;                             \
        _Pragma("unroll")                                                       \
        for (int i_ = 0; i_ < 8; i_++) {                                        \
            int idx_ = tid + i_ * 256;                                          \
            int r_ = idx_ >> 3, q_ = idx_ & 7;                                  \
            cpa16(ba_ + (r_ * FPITCH + q_ * 8) * 2,                             \
                  A + (size_t)(row0 + r_) * HID + (kc) * 64 + q_ * 8);          \
        }                                                                       \
        { int r_ = tid >> 3, q_ = tid & 7;                                      \
          cpa16(bb_ + (r_ * FPITCH + q_ * 8) * 2,                               \
                g_decw + (size_t)r_ * HID + (kc) * 64 + q_ * 8); }              \
        asm volatile("cp.async.commit_group;");                                 \
    } while (0)

    LDD_(0);
#pragma unroll
    for (int kc = 0; kc < 4; kc++) {
        if (kc + 1 < 4) { LDD_(kc + 1); asm volatile("cp.async.wait_group 1;"); }
        else            { asm volatile("cp.async.wait_group 0;"); }
        __syncthreads();
        uint32_t ba = s0 + (kc & 1) * DA_BYTES;
        uint32_t bb = sB0 + (kc & 1) * DB_BYTES;
#pragma unroll
        for (int ks = 0; ks < 4; ks++) {
            uint32_t a[2][4];
#pragma unroll
            for (int mt = 0; mt < 2; mt++)
                ldsm4(a[mt], ba + aoff + (mt * 16 * FPITCH + ks * 16) * 2);
            uint32_t b[4][2];
#pragma unroll
            for (int np = 0; np < 2; np++) {
                uint32_t r[4];
                ldsm4(r, bb + boff + (np * 16 * FPITCH + ks * 16) * 2);
                b[2 * np][0] = r[0]; b[2 * np][1] = r[1];
                b[2 * np + 1][0] = r[2]; b[2 * np + 1][1] = r[3];
            }
#pragma unroll
            for (int mt = 0; mt < 2; mt++)
#pragma unroll
                for (int nt = 0; nt < 4; nt++)
                    mma_f16(d[mt][nt], a[mt], b[nt]);
        }
        __syncthreads();
    }
#undef LDD_

#pragma unroll
    for (int nt = 0; nt < 4; nt++) {
        int col = nt * 8 + 2 * tig;
        float b0 = bias[col], b1 = bias[col + 1];
#pragma unroll
        for (int mt = 0; mt < 2; mt++) {
            int rowa = row0 + wid * 32 + mt * 16 + gq;
#pragma unroll
            for (int half = 0; half < 2; half++) {
                int row = rowa + half * 8;
                *(float2*)(C + (size_t)row * N_ACTIONS + col) =
                    make_float2(d[mt][nt][half * 2] + b0, d[mt][nt][half * 2 + 1] + b1);
            }
        }
    }
}

// ================= split prep kernels =================
#define N_OBS4 (ROWS * OBS_DIM / 4)
#define N_H04  (ROWS * HID / 4)
#define PREP_MAIN_TOTAL (N_OBS4 + 32768)
#define PREP_REST_TOTAL (N_H04 + 524288 + 262144 + 196608 + 8192 + 1024)

__global__ void prep_main(const float* __restrict__ obs, const float* __restrict__ enc_w)
{
    int idx = blockIdx.x * blockDim.x + threadIdx.x;
    if (idx < N_OBS4) {
        float4 v = ((const float4*)obs)[idx];
        ((__half2*)g_obs16)[2 * idx]     = __floats2half2_rn(v.x, v.y);
        ((__half2*)g_obs16)[2 * idx + 1] = __floats2half2_rn(v.z, v.w);
        return;
    }
    idx -= N_OBS4;
    if (idx < 32768) g_encw[idx] = __float2half_rn(enc_w[idx]);
}

__global__ void prep_rest(const float* __restrict__ h0,
                          const float* __restrict__ w_ih, const float* __restrict__ w_hh,
                          const float* __restrict__ b_ih, const float* __restrict__ b_hh,
                          const float* __restrict__ dec_w)
{
    int idx = blockIdx.x * blockDim.x + threadIdx.x;
    const float inv = 1.0f / (float)N_AGENTS;
    if (idx < N_H04) {
        float4 v = ((const float4*)h0)[idx];
        ((__half2*)g_h016)[2 * idx]     = __floats2half2_rn(v.x, v.y);
        ((__half2*)g_h016)[2 * idx + 1] = __floats2half2_rn(v.z, v.w);
        return;
    }
    idx -= N_H04;
    if (idx < 524288) {
        int c = idx >> 9, k = idx & 511;
        int g = (c >> 3) & 3;
        int j = ((c >> 5) << 3) + (c & 7);
        float v;
        if (g == 0)      v = (k < 256) ? w_ih[j * 256 + k]         : w_hh[j * 256 + k - 256];
        else if (g == 1) v = (k < 256) ? w_ih[(256 + j) * 256 + k] : w_hh[(256 + j) * 256 + k - 256];
        else if (g == 2) v = (k < 256) ? w_ih[(512 + j) * 256 + k] : 0.0f;
        else             v = (k < 256) ? 0.0f                      : w_hh[(512 + j) * 256 + k - 256];
        g_wf[c * 512 + k] = __float2half_rn(v);
        return;
    }
    idx -= 524288;
    if (idx < 262144) {
        int c = idx >> 8, k = idx & 255;
        int g = (c >> 3) & 3;
        int j = ((c >> 5) << 3) + (c & 7);
        float v;
        if (g == 0)      v = w_hh[j * 256 + k]         - w_ih[j * 256 + k] * inv;
        else if (g == 1) v = w_hh[(256 + j) * 256 + k] - w_ih[(256 + j) * 256 + k] * inv;
        else if (g == 2) v = -w_ih[(512 + j) * 256 + k] * inv;
        else             v = w_hh[(512 + j) * 256 + k];
        g_wf2[c * 256 + k] = __float2half_rn(v);
        return;
    }
    idx -= 262144;
    if (idx < 196608) { g_ws16[idx] = __float2half_rn(w_ih[idx] * inv); return; }
    idx -= 196608;
    if (idx < 8192)   { g_decw[idx] = __float2half_rn(dec_w[idx]); return; }
    idx -= 8192;
    if (idx < 1024) {
        int g = idx >> 8, j = idx & 255;
        float v;
        if (g == 0)      v = b_ih[j] + b_hh[j];
        else if (g == 1) v = b_ih[256 + j] + b_hh[256 + j];
        else if (g == 2) v = b_ih[512 + j];
        else             v = b_hh[512 + j];
        g_gb[idx] = v;
    }
}

extern "C" void kernel_launch(void* const* d_in, const int* in_sizes, int n_in,
                              void* d_out, int out_size)
{
    const float* obs   = (const float*)d_in[0];
    const float* h0    = (const float*)d_in[1];
    const float* enc_w = (const float*)d_in[2];
    const float* enc_b = (const float*)d_in[3];
    const float* w_ih  = (const float*)d_in[4];
    const float* w_hh  = (const float*)d_in[5];
    const float* b_ih  = (const float*)d_in[6];
    const float* b_hh  = (const float*)d_in[7];
    const float* dec_w = (const float*)d_in[8];
    const float* dec_b = (const float*)d_in[9];
    float* out = (float*)d_out;

    __half *x16, *h16a, *h16b, *obs16, *h016, *ws16, *S16;
    float *Sg;
    cudaGetSymbolAddress((void**)&x16,   g_x16);
    cudaGetSymbolAddress((void**)&h16a,  g_h16a);
    cudaGetSymbolAddress((void**)&h16b,  g_h16b);
    cudaGetSymbolAddress((void**)&obs16, g_obs16);
    cudaGetSymbolAddress((void**)&h016,  g_h016);
    cudaGetSymbolAddress((void**)&ws16,  g_ws16);
    cudaGetSymbolAddress((void**)&S16,   g_S16);
    cudaGetSymbolAddress((void**)&Sg,    g_Sg);

    cudaFuncSetAttribute(fused_gru,  cudaFuncAttributeMaxDynamicSharedMemorySize, FSMEM_BYTES);
    cudaFuncSetAttribute(fused_gru2, cudaFuncAttributeMaxDynamicSharedMemorySize, FSMEM_BYTES);
    cudaFuncSetAttribute(enc2,       cudaFuncAttributeMaxDynamicSharedMemorySize, FSMEM_BYTES);
    cudaFuncSetAttribute(hgemm64,    cudaFuncAttributeMaxDynamicSharedMemorySize, SG_SMEM);
    cudaFuncSetAttribute(dec_gemm,   cudaFuncAttributeMaxDynamicSharedMemorySize, DEC_SMEM);

    dim3 t(256);

    cudaStream_t s2;
    cudaEvent_t evFork, evJoin;
    cudaStreamCreateWithFlags(&s2, cudaStreamNonBlocking);
    cudaEventCreateWithFlags(&evFork, cudaEventDisableTiming);
    cudaEventCreateWithFlags(&evJoin, cudaEventDisableTiming);

    cudaEventRecord(evFork, 0);
    cudaStreamWaitEvent(s2, evFork, 0);
    prep_rest<<<(PREP_REST_TOTAL + 255) / 256, 256, 0, s2>>>(h0, w_ih, w_hh, b_ih, b_hh, dec_w);
    cudaEventRecord(evJoin, s2);

    prep_main<<<(PREP_MAIN_TOTAL + 255) / 256, 256>>>(obs, enc_w);
    enc2<<<dim3(2, ROWS / 256), t, FSMEM_BYTES>>>(obs16, enc_b, x16);

    cudaStreamWaitEvent(0, evJoin, 0);

    // cell 1 (fp16 hprev = h016), fused group-sum -> S16
    fused_gru<<<dim3(8, ROWS / 128), t, FSMEM_BYTES>>>(x16, h016, h016, h16a, S16);

    // comm 1 GEMM + cell 2 (fused sum -> S16 for comm 2)
    hgemm64<<<dim3(6, NGROUP / 64), 128, SG_SMEM>>>(S16, ws16, Sg);
    fused_gru2<<<dim3(8, ROWS / 128), t, FSMEM_BYTES>>>(h16a, h16a, Sg, nullptr, h16b, S16);

    // comm 2 GEMM + cell 3 (fp32 h straight into d_out tail, no sum)
    hgemm64<<<dim3(6, NGROUP / 64), 128, SG_SMEM>>>(S16, ws16, Sg);
    fused_gru2<<<dim3(8, ROWS / 128), t, FSMEM_BYTES>>>(h16b, h16b, Sg,
                                                        out + (size_t)ROWS * N_ACTIONS, h16a, nullptr);

    // decoder (dedicated N=32 kernel)
    dec_gemm<<<dim3(1, ROWS / 256), t, DEC_SMEM>>>(h16a, dec_b, out);

    cudaEventDestroy(evFork);
    cudaEventDestroy(evJoin);
    cudaStreamDestroy(s2);
}